// round 1
// baseline (speedup 1.0000x reference)
#include <cuda_runtime.h>
#include <cstdint>

#define BATCH 16
#define CIN   512
#define COUT  512
#define NPIX  4096
#define MOD_SCALE  0.044194173824159216f
#define CONV_SCALE 0.014731391274719739f

#define XH    13056   // 32 ci * 408 (6 rows * 68 cols, padded stride)
#define XSTR  408
#define WTILE 4096    // 128 o * 32 ci packed frags
#define CONV_SMEM (2*XH*4 + 2*WTILE*4)   // 137216 bytes

// ---------------- device scratch ----------------
__device__ float g_s[BATCH*CIN];
__device__ float g_wsq[COUT*CIN];
__device__ float g_dscale[BATCH*COUT];
__device__ float g_wpack[9*COUT*CIN];          // 9.4 MB, frag-packed tf32
__device__ float g_xs[BATCH*CIN*NPIX];         // 134 MB, s-scaled tf32 input

__device__ __forceinline__ float tf32_rna(float x){
    uint32_t u;
    asm("cvt.rna.tf32.f32 %0, %1;" : "=r"(u) : "f"(x));
    return __uint_as_float(u);
}

// ---------------- s[b][ci] = style @ (mod_weight*MOD_SCALE)^T + bias ----------------
__global__ void mod_kernel(const float* __restrict__ style,
                           const float* __restrict__ mod_weight,
                           const float* __restrict__ mod_bias){
    __shared__ float st[512];
    int b = blockIdx.x, t = threadIdx.x;
    st[t] = style[b*512 + t];
    __syncthreads();
    const float* wr = mod_weight + t*512;
    float acc = 0.f;
    #pragma unroll 8
    for (int j = 0; j < 512; j++) acc = fmaf(st[j], wr[j], acc);
    g_s[b*512 + t] = acc * MOD_SCALE + mod_bias[t];
}

// ---------------- wsq[o][ci] = sum_t weight^2 ----------------
__global__ void wsq_kernel(const float* __restrict__ w){
    int i = blockIdx.x*blockDim.x + threadIdx.x;   // 262144
    const float* p = w + i*9;
    float a = 0.f;
    #pragma unroll
    for (int t = 0; t < 9; t++) a = fmaf(p[t], p[t], a);
    g_wsq[i] = a;
}

// ---------------- dscale[b][o] = CONV_SCALE * rsqrt(CONV_SCALE^2 * sum s^2*wsq + 1e-8) ----------------
__global__ void demod_kernel(){
    __shared__ float s2[512];
    int b = blockIdx.x, t = threadIdx.x;
    float sv = g_s[b*512 + t];
    s2[t] = sv*sv;
    __syncthreads();
    const float* wr = g_wsq + t*512;
    float acc = 0.f;
    #pragma unroll 8
    for (int j = 0; j < 512; j++) acc = fmaf(s2[j], wr[j], acc);
    float v = CONV_SCALE*CONV_SCALE*acc + 1e-8f;
    g_dscale[b*512 + t] = CONV_SCALE / sqrtf(v);
}

// ---------------- pack W into mma-fragment layout, tf32-rounded ----------------
// layout: [tap][cic(16)][ob(4)][ks(4)][mt(8)][lane(32)][reg(4)]
__global__ void pack_kernel(const float* __restrict__ w){
    int i = blockIdx.x*256 + threadIdx.x;          // 2359296 = 512*512*9, coalesced read
    int o   = i / 4608;
    int rem = i - o*4608;
    int ci  = rem / 9;
    int tap = rem - ci*9;
    int cic = ci >> 5, ks = (ci >> 3) & 3;
    int ob  = o  >> 7, mt = (o  >> 4) & 7;
    int lane = ((o & 7) << 2) | (ci & 3);
    int reg  = ((o >> 3) & 1) | (((ci >> 2) & 1) << 1);
    int q = (((tap*16 + cic)*4 + ob) << 12) + ((((ks*8 + mt) << 5) + lane) << 2) + reg;
    g_wpack[q] = tf32_rna(w[i]);
}

// ---------------- xs = tf32_rna(s[b,ci] * x) ----------------
__global__ void xscale_kernel(const float4* __restrict__ x){
    int i = blockIdx.x*blockDim.x + threadIdx.x;   // 8388608 float4
    int bc = i >> 10;                              // 1024 float4 per (b,ci) plane
    float s = g_s[bc];
    float4 v = x[i];
    v.x = tf32_rna(v.x * s);
    v.y = tf32_rna(v.y * s);
    v.z = tf32_rna(v.z * s);
    v.w = tf32_rna(v.w * s);
    ((float4*)g_xs)[i] = v;
}

// ---------------- main implicit conv (per-batch GEMM, 9 taps per ci-chunk) ----------------
__device__ __forceinline__ void mma_tf32(float* c, uint32_t a0,uint32_t a1,uint32_t a2,uint32_t a3,
                                         uint32_t b0,uint32_t b1){
    asm volatile("mma.sync.aligned.m16n8k8.row.col.f32.tf32.tf32.f32 "
        "{%0,%1,%2,%3}, {%4,%5,%6,%7}, {%8,%9}, {%0,%1,%2,%3};"
        : "+f"(c[0]), "+f"(c[1]), "+f"(c[2]), "+f"(c[3])
        : "r"(a0), "r"(a1), "r"(a2), "r"(a3), "r"(b0), "r"(b1));
}

__global__ __launch_bounds__(256,1) void conv_kernel(float* __restrict__ out){
    extern __shared__ float smem[];
    float* sX = smem;                 // [2][13056]  halo tiles
    float* sW = smem + 2*XH;          // [2][4096]   packed W frags

    const int tid  = threadIdx.x;
    const int lane = tid & 31;
    const int warp = tid >> 5;
    const int wm   = warp >> 2;       // 0..1  (64 out-ch each)
    const int wn   = warp & 3;        // 0..3  (one image row each)
    const int ob = blockIdx.x;        // out-ch block (128)
    const int rt = blockIdx.y;        // row tile (4 rows)
    const int b  = blockIdx.z;        // batch
    const int r0 = rt * 4;

    unsigned sx_u = (unsigned)__cvta_generic_to_shared(sX);
    unsigned sw_u = (unsigned)__cvta_generic_to_shared(sW);

    const float* xg = g_xs + (size_t)b * (CIN*NPIX);

    float acc[4][8][4];
    #pragma unroll
    for (int i=0;i<4;i++)
      #pragma unroll
      for (int j=0;j<8;j++)
        #pragma unroll
        for (int k=0;k<4;k++) acc[i][j][k]=0.f;

    auto load_x = [&](int chunk){
        unsigned sb = sx_u + (unsigned)((chunk & 1) * XH) * 4u;
        const float* gx = xg + chunk * 32 * NPIX;
        for (int i = tid; i < XH; i += 256){
            int ci  = i / XSTR;
            int rem = i - ci * XSTR;
            int r = rem / 68;
            int c = rem - r * 68;
            int grow = r0 - 1 + r;
            int gcol = c - 1;
            bool ok = ((unsigned)grow < 64u) && ((unsigned)gcol < 64u);
            const float* ga = gx + ci * NPIX + (ok ? (grow * 64 + gcol) : 0);
            int sz = ok ? 4 : 0;
            asm volatile("cp.async.ca.shared.global [%0], [%1], 4, %2;"
                         :: "r"(sb + (unsigned)i * 4u), "l"(ga), "r"(sz));
        }
    };

    auto load_w = [&](int step){
        int chunk = step / 9;
        int tap   = step - chunk * 9;
        const float* gw = g_wpack + (((tap*16 + chunk)*4 + ob) << 12);
        unsigned sb = sw_u + (unsigned)((step & 1) * WTILE) * 4u;
        #pragma unroll
        for (int i = 0; i < 4; i++){
            int idx = tid + i * 256;
            asm volatile("cp.async.cg.shared.global [%0], [%1], 16;"
                         :: "r"(sb + (unsigned)idx * 16u), "l"(gw + idx * 4));
        }
    };

    load_x(0);
    load_w(0);
    asm volatile("cp.async.commit_group;");
    asm volatile("cp.async.wait_group 0;");
    __syncthreads();

    for (int step = 0; step < 144; step++){        // 16 ci-chunks * 9 taps
        int chunk = step / 9;
        int tap   = step - chunk * 9;
        if (tap == 0 && chunk < 15) load_x(chunk + 1);
        if (step < 143) load_w(step + 1);
        asm volatile("cp.async.commit_group;");

        const int dh = tap / 3;
        const int dw = tap - dh * 3;
        const float* xb = sX + (chunk & 1) * XH + (wn + dh) * 68 + dw + (lane >> 2);
        const float4* w4 = (const float4*)(sW + (step & 1) * WTILE);

        #pragma unroll
        for (int ks = 0; ks < 4; ks++){
            const float* xp = xb + (ks * 8 + (lane & 3)) * XSTR;
            uint32_t bf[8][2];
            #pragma unroll
            for (int nt = 0; nt < 8; nt++){
                bf[nt][0] = __float_as_uint(xp[nt*8]);
                bf[nt][1] = __float_as_uint(xp[nt*8 + 4*XSTR]);
            }
            #pragma unroll
            for (int mt = 0; mt < 4; mt++){
                float4 a = w4[(ks*8 + wm*4 + mt)*32 + lane];
                uint32_t a0=__float_as_uint(a.x), a1=__float_as_uint(a.y),
                         a2=__float_as_uint(a.z), a3=__float_as_uint(a.w);
                #pragma unroll
                for (int nt = 0; nt < 8; nt++)
                    mma_tf32(acc[mt][nt], a0,a1,a2,a3, bf[nt][0], bf[nt][1]);
            }
        }
        asm volatile("cp.async.wait_group 0;");
        __syncthreads();
    }

    // epilogue: scale by dscale[b][o] and store
    const int rowpx = (r0 + wn) * 64;
    #pragma unroll
    for (int mt = 0; mt < 4; mt++){
        int o0 = ob*128 + wm*64 + mt*16 + (lane >> 2);
        float d0 = g_dscale[b*512 + o0];
        float d1 = g_dscale[b*512 + o0 + 8];
        float* p0 = out + (size_t)(b*512 + o0) * NPIX + rowpx + (lane & 3)*2;
        float* p1 = p0 + (size_t)8 * NPIX;
        #pragma unroll
        for (int nt = 0; nt < 8; nt++){
            float2 v0 = make_float2(acc[mt][nt][0]*d0, acc[mt][nt][1]*d0);
            float2 v1 = make_float2(acc[mt][nt][2]*d1, acc[mt][nt][3]*d1);
            *(float2*)(p0 + nt*8) = v0;
            *(float2*)(p1 + nt*8) = v1;
        }
    }
}

// ---------------- launcher ----------------
extern "C" void kernel_launch(void* const* d_in, const int* in_sizes, int n_in,
                              void* d_out, int out_size){
    const float* input      = (const float*)d_in[0];
    const float* style      = (const float*)d_in[1];
    const float* weight     = (const float*)d_in[2];
    const float* mod_weight = (const float*)d_in[3];
    const float* mod_bias   = (const float*)d_in[4];
    float* out = (float*)d_out;

    cudaFuncSetAttribute(conv_kernel, cudaFuncAttributeMaxDynamicSharedMemorySize, CONV_SMEM);

    mod_kernel   <<<16, 512>>>(style, mod_weight, mod_bias);
    wsq_kernel   <<<1024, 256>>>(weight);
    demod_kernel <<<16, 512>>>();
    pack_kernel  <<<9216, 256>>>(weight);
    xscale_kernel<<<8192, 1024>>>((const float4*)input);
    conv_kernel  <<<dim3(4,16,16), 256, CONV_SMEM>>>(out);
}